// round 15
// baseline (speedup 1.0000x reference)
#include <cuda_runtime.h>
#include <math.h>
#include <stdint.h>

// Problem constants
#define BB 1024
#define SS 64
#define DD 512
#define RR 16
#define CC 1000

// ---------------------------------------------------------------------------
// Scratch (__device__ globals; float4 for 16B alignment needed by cp.async)
// ---------------------------------------------------------------------------
__device__ float4 g_lrc4  [(size_t)BB * DD * RR / 4];  // low_rank_cov [B, D*R]
__device__ float4 g_std4  [(size_t)BB * DD / 4];       // diagonal_std [B, D]
__device__ float4 g_pre4  [(size_t)BB * SS * DD / 4];  // pre_logits [B*S, D] (tf32-rounded)
__device__ float4 g_wcov4 [(size_t)DD * RR * DD / 4];  // tf32-rounded W_cov
__device__ float4 g_wcls4 [(size_t)CC * DD / 4];       // tf32-rounded W_cls
__device__ float4 g_wdiag4[(size_t)DD * DD / 4];       // tf32-rounded W_diag
__device__ float4 g_feat4 [(size_t)BB * DD / 4];       // tf32-rounded features

// ---------------------------------------------------------------------------
// Helpers
// ---------------------------------------------------------------------------
__device__ __forceinline__ uint32_t smem_u32(const void* p) {
    uint32_t a;
    asm("{ .reg .u64 t; cvta.to.shared.u64 t, %1; cvt.u32.u64 %0, t; }"
        : "=r"(a) : "l"(p));
    return a;
}
__device__ __forceinline__ float rtf32(float x) {  // round-to-nearest tf32
    uint32_t o; asm("cvt.rna.tf32.f32 %0, %1;" : "=r"(o) : "f"(x));
    return __uint_as_float(o);
}
__device__ __forceinline__ void cpa16(uint32_t dst, const void* src, uint32_t sz) {
    asm volatile("cp.async.cg.shared.global [%0], [%1], 16, %2;"
                 :: "r"(dst), "l"(src), "r"(sz) : "memory");
}
// m16n8k8 tf32 MMA (legacy HMMA path; legal on base sm_103 target)
__device__ __forceinline__ void mma8(float* d, const uint32_t* a, const uint32_t* b) {
    asm volatile(
        "mma.sync.aligned.m16n8k8.row.col.f32.tf32.tf32.f32 "
        "{%0,%1,%2,%3}, {%4,%5,%6,%7}, {%8,%9}, {%0,%1,%2,%3};"
        : "+f"(d[0]), "+f"(d[1]), "+f"(d[2]), "+f"(d[3])
        : "r"(a[0]), "r"(a[1]), "r"(a[2]), "r"(a[3]), "r"(b[0]), "r"(b[1]));
}
// ldmatrix x4 (b16 view; one m8n8.b16 tile == one 8x4 tf32 fragment tile)
__device__ __forceinline__ void ldsm4(uint32_t* r, uint32_t addr) {
    asm volatile("ldmatrix.sync.aligned.m8n8.x4.shared.b16 {%0,%1,%2,%3}, [%4];"
        : "=r"(r[0]), "=r"(r[1]), "=r"(r[2]), "=r"(r[3]) : "r"(addr));
}

#define KSLAB 32
#define STGS  3
#define AHEAD 2
#define PAD   36
#define STAGE_FLOATS (2 * 128 * PAD)
#define BOFF  (128 * PAD)
#define MMA_SMEM (STGS * STAGE_FLOATS * 4 + 512)   // 111104 B -> 2 CTAs/SM

// ---------------------------------------------------------------------------
// G3 kernel: C = A @ B^T + bias, EPI = x*(2/3).  N=1000 needs guards.
// 8 warps (4m x 2n), warp 32x64, 256 threads, 2 CTAs/SM (16 warps/SM).
// ---------------------------------------------------------------------------
__global__ __launch_bounds__(256, 2) void mma_gemm_g3(
    const float* __restrict__ A, const float* __restrict__ Bm,
    const float* __restrict__ bias, float* __restrict__ Cm,
    int M, int N, int K)
{
    extern __shared__ float sm[];
    float* s_bias = sm + STGS * STAGE_FLOATS;

    const int tid = threadIdx.x;
    const int bm  = blockIdx.y * 128;
    const int bn  = blockIdx.x * 128;

    if (tid < 128) s_bias[tid] = (bn + tid < N) ? bias[bn + tid] : 0.f;

    const int wid = tid >> 5, lane = tid & 31;
    const int wm  = (wid & 3) * 32;
    const int wn  = (wid >> 2) * 64;
    const int g   = lane >> 2;
    const int t   = lane & 3;

    const uint32_t smb = smem_u32(sm);

    const int tile = lane >> 3, rit = lane & 7;
    uint32_t aoff[2], boff[4];
#pragma unroll
    for (int mt = 0; mt < 2; mt++)
        aoff[mt] = (uint32_t)(((wm + mt * 16 + ((tile & 1) << 3) + rit) * PAD
                               + ((tile >> 1) << 2)) * 4);
#pragma unroll
    for (int p = 0; p < 4; p++)
        boff[p] = (uint32_t)((BOFF + (wn + p * 16 + ((tile >> 1) << 3) + rit) * PAD
                               + ((tile & 1) << 2)) * 4);

    auto load_slab = [&](int s, int slab) {
        const int k0 = slab * KSLAB;
        const uint32_t abase = smb + (uint32_t)(s * STAGE_FLOATS) * 4u;
        const uint32_t bbase = abase + BOFF * 4u;
#pragma unroll
        for (int q = 0; q < 4; q++) {
            int idx = tid + q * 256;
            int m = idx >> 3, kc = idx & 7;
            cpa16(abase + (uint32_t)(m * PAD + kc * 4) * 4u,
                  A + (size_t)(bm + m) * K + k0 + kc * 4, 16);
        }
#pragma unroll
        for (int q = 0; q < 4; q++) {
            int idx = tid + q * 256;
            int n = idx >> 3, kc = idx & 7;
            int gn = bn + n;
            uint32_t sz = (gn < N) ? 16u : 0u;
            int gc = (gn < N) ? gn : (N - 1);
            cpa16(bbase + (uint32_t)(n * PAD + kc * 4) * 4u,
                  Bm + (size_t)gc * K + k0 + kc * 4, sz);
        }
    };

    float acc[2][8][4];
#pragma unroll
    for (int i = 0; i < 2; i++)
#pragma unroll
        for (int j = 0; j < 8; j++)
#pragma unroll
            for (int c = 0; c < 4; c++) acc[i][j][c] = 0.f;

    const int nslab = K / KSLAB;
    for (int p = 0; p < AHEAD; p++) {
        load_slab(p, p);
        asm volatile("cp.async.commit_group;" ::: "memory");
    }

    for (int j = 0; j < nslab; j++) {
        asm volatile("cp.async.wait_group 1;" ::: "memory");
        __syncthreads();
        if (j + AHEAD < nslab) load_slab((j + AHEAD) % STGS, j + AHEAD);
        asm volatile("cp.async.commit_group;" ::: "memory");

        const uint32_t stg = smb + (uint32_t)((j % STGS) * STAGE_FLOATS) * 4u;

#pragma unroll
        for (int ks = 0; ks < 4; ks++) {
            const uint32_t kb = stg + (uint32_t)ks * 32u;
            uint32_t af[2][4], bf[4][4];
            ldsm4(af[0], kb + aoff[0]);
            ldsm4(af[1], kb + aoff[1]);
#pragma unroll
            for (int p = 0; p < 4; p++) ldsm4(bf[p], kb + boff[p]);
#pragma unroll
            for (int mt = 0; mt < 2; mt++)
#pragma unroll
                for (int nt = 0; nt < 8; nt++)
                    mma8(acc[mt][nt], af[mt], &bf[nt >> 1][(nt & 1) << 1]);
        }
    }

#pragma unroll
    for (int mt = 0; mt < 2; mt++) {
        const int r0 = bm + wm + mt * 16 + g;
#pragma unroll
        for (int nt = 0; nt < 8; nt++) {
            const int lc = wn + nt * 8 + 2 * t;
            const int gc = bn + lc;
            float b0 = s_bias[lc], b1 = s_bias[lc + 1];
            float v00 = (acc[mt][nt][0] + b0) * (2.0f / 3.0f);
            float v01 = (acc[mt][nt][1] + b1) * (2.0f / 3.0f);
            float v10 = (acc[mt][nt][2] + b0) * (2.0f / 3.0f);
            float v11 = (acc[mt][nt][3] + b1) * (2.0f / 3.0f);
            if (gc + 1 < N) {
                *(float2*)(Cm + (size_t)r0 * N + gc)       = make_float2(v00, v01);
                *(float2*)(Cm + (size_t)(r0 + 8) * N + gc) = make_float2(v10, v11);
            } else if (gc < N) {
                Cm[(size_t)r0 * N + gc]       = v00;
                Cm[(size_t)(r0 + 8) * N + gc] = v10;
            }
        }
    }
}

// ---------------------------------------------------------------------------
// Dual GEMM (G1 + G2 in one launch): blocks x<NB1 -> lrc (plain epi),
// blocks x>=NB1 -> stdv (softplus epi). All N multiples of 128 (no guards).
// ---------------------------------------------------------------------------
#define NB1 64    // (DD*RR)/128 n-blocks for G1; G2 adds DD/128 = 4

__global__ __launch_bounds__(256, 2) void mma_gemm_dual(
    const float* __restrict__ A,
    const float* __restrict__ B1, const float* __restrict__ bias1,
    float* __restrict__ C1,
    const float* __restrict__ B2, const float* __restrict__ bias2,
    float* __restrict__ C2,
    int M, int K)
{
    extern __shared__ float sm[];
    float* s_bias = sm + STGS * STAGE_FLOATS;

    const int tid = threadIdx.x;
    const int bm  = blockIdx.y * 128;
    const bool g2 = (blockIdx.x >= NB1);
    const int bn  = (g2 ? (blockIdx.x - NB1) : blockIdx.x) * 128;
    const float* Bm   = g2 ? B2 : B1;
    const float* bias = g2 ? bias2 : bias1;
    float* Cm         = g2 ? C2 : C1;
    const int N       = g2 ? DD : DD * RR;

    if (tid < 128) s_bias[tid] = bias[bn + tid];

    const int wid = tid >> 5, lane = tid & 31;
    const int wm  = (wid & 3) * 32;
    const int wn  = (wid >> 2) * 64;
    const int g   = lane >> 2;
    const int t   = lane & 3;

    const uint32_t smb = smem_u32(sm);

    const int tile = lane >> 3, rit = lane & 7;
    uint32_t aoff[2], boff[4];
#pragma unroll
    for (int mt = 0; mt < 2; mt++)
        aoff[mt] = (uint32_t)(((wm + mt * 16 + ((tile & 1) << 3) + rit) * PAD
                               + ((tile >> 1) << 2)) * 4);
#pragma unroll
    for (int p = 0; p < 4; p++)
        boff[p] = (uint32_t)((BOFF + (wn + p * 16 + ((tile >> 1) << 3) + rit) * PAD
                               + ((tile & 1) << 2)) * 4);

    auto load_slab = [&](int s, int slab) {
        const int k0 = slab * KSLAB;
        const uint32_t abase = smb + (uint32_t)(s * STAGE_FLOATS) * 4u;
        const uint32_t bbase = abase + BOFF * 4u;
#pragma unroll
        for (int q = 0; q < 4; q++) {
            int idx = tid + q * 256;
            int m = idx >> 3, kc = idx & 7;
            cpa16(abase + (uint32_t)(m * PAD + kc * 4) * 4u,
                  A + (size_t)(bm + m) * K + k0 + kc * 4, 16);
        }
#pragma unroll
        for (int q = 0; q < 4; q++) {
            int idx = tid + q * 256;
            int n = idx >> 3, kc = idx & 7;
            cpa16(bbase + (uint32_t)(n * PAD + kc * 4) * 4u,
                  Bm + (size_t)(bn + n) * K + k0 + kc * 4, 16);
        }
    };

    float acc[2][8][4];
#pragma unroll
    for (int i = 0; i < 2; i++)
#pragma unroll
        for (int j = 0; j < 8; j++)
#pragma unroll
            for (int c = 0; c < 4; c++) acc[i][j][c] = 0.f;

    const int nslab = K / KSLAB;
    for (int p = 0; p < AHEAD; p++) {
        load_slab(p, p);
        asm volatile("cp.async.commit_group;" ::: "memory");
    }

    for (int j = 0; j < nslab; j++) {
        asm volatile("cp.async.wait_group 1;" ::: "memory");
        __syncthreads();
        if (j + AHEAD < nslab) load_slab((j + AHEAD) % STGS, j + AHEAD);
        asm volatile("cp.async.commit_group;" ::: "memory");

        const uint32_t stg = smb + (uint32_t)((j % STGS) * STAGE_FLOATS) * 4u;

#pragma unroll
        for (int ks = 0; ks < 4; ks++) {
            const uint32_t kb = stg + (uint32_t)ks * 32u;
            uint32_t af[2][4], bf[4][4];
            ldsm4(af[0], kb + aoff[0]);
            ldsm4(af[1], kb + aoff[1]);
#pragma unroll
            for (int p = 0; p < 4; p++) ldsm4(bf[p], kb + boff[p]);
#pragma unroll
            for (int mt = 0; mt < 2; mt++)
#pragma unroll
                for (int nt = 0; nt < 8; nt++)
                    mma8(acc[mt][nt], af[mt], &bf[nt >> 1][(nt & 1) << 1]);
        }
    }

#pragma unroll
    for (int mt = 0; mt < 2; mt++) {
        const int r0 = bm + wm + mt * 16 + g;
#pragma unroll
        for (int nt = 0; nt < 8; nt++) {
            const int lc = wn + nt * 8 + 2 * t;
            const int gc = bn + lc;
            float b0 = s_bias[lc], b1 = s_bias[lc + 1];
            float v00 = acc[mt][nt][0] + b0, v01 = acc[mt][nt][1] + b1;
            float v10 = acc[mt][nt][2] + b0, v11 = acc[mt][nt][3] + b1;
            if (g2) {   // uniform branch per block
                v00 = fmaxf(v00, 0.f) + log1pf(expf(-fabsf(v00))) + 1e-3f;
                v01 = fmaxf(v01, 0.f) + log1pf(expf(-fabsf(v01))) + 1e-3f;
                v10 = fmaxf(v10, 0.f) + log1pf(expf(-fabsf(v10))) + 1e-3f;
                v11 = fmaxf(v11, 0.f) + log1pf(expf(-fabsf(v11))) + 1e-3f;
            }
            *(float2*)(Cm + (size_t)r0 * N + gc)       = make_float2(v00, v01);
            *(float2*)(Cm + (size_t)(r0 + 8) * N + gc) = make_float2(v10, v11);
        }
    }
}

// ---------------------------------------------------------------------------
// tf32 RN rounding: 3-segment (pre-dual inputs) + single-segment (wcls)
// ---------------------------------------------------------------------------
__global__ void round_tf32_seg3(
    const float4* __restrict__ s0, float4* __restrict__ d0, int n0,
    const float4* __restrict__ s1, float4* __restrict__ d1, int n1,
    const float4* __restrict__ s2, float4* __restrict__ d2, int n2)
{
    int i = blockIdx.x * blockDim.x + threadIdx.x;
    const float4* s; float4* d; int k;
    if (i < n0)                { s = s0; d = d0; k = i; }
    else if (i < n0 + n1)      { s = s1; d = d1; k = i - n0; }
    else if (i < n0 + n1 + n2) { s = s2; d = d2; k = i - n0 - n1; }
    else return;
    float4 v = s[k];
    v.x = rtf32(v.x); v.y = rtf32(v.y); v.z = rtf32(v.z); v.w = rtf32(v.w);
    d[k] = v;
}

__global__ void round_tf32_one(const float4* __restrict__ s, float4* __restrict__ d, int n)
{
    int i = blockIdx.x * blockDim.x + threadIdx.x;
    if (i >= n) return;
    float4 v = s[i];
    v.x = rtf32(v.x); v.y = rtf32(v.y); v.z = rtf32(v.z); v.w = rtf32(v.w);
    d[i] = v;
}

// ---------------------------------------------------------------------------
// pre[b,s,d] = f + std*nd + sum_r lrc*nlr   (tf32-rounded output)
// One block per b: 256 threads x 2d, all 64 s. lrc read ONCE (halved traffic).
// ---------------------------------------------------------------------------
__global__ __launch_bounds__(256, 3) void prelogits_kernel(
    const float* __restrict__ features, const float* __restrict__ lrc,
    const float* __restrict__ stdv, const float* __restrict__ nd,
    const float* __restrict__ nlr, float* __restrict__ pre)
{
    const int b   = blockIdx.x;
    const int tid = threadIdx.x;
    const int d0  = tid << 1;

    float lr[2][16];
    const float4* lp = (const float4*)(lrc + ((size_t)b * DD + d0) * RR);
#pragma unroll
    for (int i = 0; i < 2; i++)
#pragma unroll
        for (int q = 0; q < 4; q++) {
            float4 v = lp[i * 4 + q];
            lr[i][q * 4 + 0] = v.x; lr[i][q * 4 + 1] = v.y;
            lr[i][q * 4 + 2] = v.z; lr[i][q * 4 + 3] = v.w;
        }
    const float2 f2  = *(const float2*)(features + (size_t)b * DD + d0);
    const float2 sd2 = *(const float2*)(stdv     + (size_t)b * DD + d0);

    const size_t row0 = (size_t)b * SS;
#pragma unroll 4
    for (int si = 0; si < SS; si++) {
        const size_t row = row0 + si;
        float nr[16];
        const float4* np = (const float4*)(nlr + row * RR);
#pragma unroll
        for (int q = 0; q < 4; q++) {
            float4 v = np[q];   // uniform across block -> L1 broadcast
            nr[q * 4 + 0] = v.x; nr[q * 4 + 1] = v.y;
            nr[q * 4 + 2] = v.z; nr[q * 4 + 3] = v.w;
        }
        const float2 ndv = *(const float2*)(nd + row * DD + d0);
        float a0 = fmaf(sd2.x, ndv.x, f2.x);
        float a1 = fmaf(sd2.y, ndv.y, f2.y);
#pragma unroll
        for (int r = 0; r < 16; r++) {
            a0 = fmaf(lr[0][r], nr[r], a0);
            a1 = fmaf(lr[1][r], nr[r], a1);
        }
        *(float2*)(pre + row * DD + d0) = make_float2(rtf32(a0), rtf32(a1));
    }
}

// ---------------------------------------------------------------------------
extern "C" void kernel_launch(void* const* d_in, const int* in_sizes, int n_in,
                              void* d_out, int out_size)
{
    const float* features   = (const float*)d_in[0];
    const float* W_cov      = (const float*)d_in[1];
    const float* b_cov      = (const float*)d_in[2];
    const float* W_diag     = (const float*)d_in[3];
    const float* b_diag     = (const float*)d_in[4];
    const float* W_cls      = (const float*)d_in[5];
    const float* b_cls      = (const float*)d_in[6];
    const float* noise_diag = (const float*)d_in[7];
    const float* noise_lr   = (const float*)d_in[8];
    float* out = (float*)d_out;

    float4 *lrc4, *std4, *pre4, *wcov4, *wcls4, *wdiag4, *feat4;
    cudaGetSymbolAddress((void**)&lrc4,   g_lrc4);
    cudaGetSymbolAddress((void**)&std4,   g_std4);
    cudaGetSymbolAddress((void**)&pre4,   g_pre4);
    cudaGetSymbolAddress((void**)&wcov4,  g_wcov4);
    cudaGetSymbolAddress((void**)&wcls4,  g_wcls4);
    cudaGetSymbolAddress((void**)&wdiag4, g_wdiag4);
    cudaGetSymbolAddress((void**)&feat4,  g_feat4);
    float* lrc  = (float*)lrc4;
    float* stdv = (float*)std4;
    float* pre  = (float*)pre4;

    cudaFuncSetAttribute(mma_gemm_g3,   cudaFuncAttributeMaxDynamicSharedMemorySize, MMA_SMEM);
    cudaFuncSetAttribute(mma_gemm_dual, cudaFuncAttributeMaxDynamicSharedMemorySize, MMA_SMEM);

    // Round the dual-GEMM inputs first (critical path)
    const int n4_feat  = BB * DD / 4;
    const int n4_wcov  = DD * RR * DD / 4;
    const int n4_wdiag = DD * DD / 4;
    const int n4_pre3  = n4_feat + n4_wcov + n4_wdiag;
    round_tf32_seg3<<<(n4_pre3 + 255) / 256, 256>>>(
        (const float4*)features, feat4,  n4_feat,
        (const float4*)W_cov,    wcov4,  n4_wcov,
        (const float4*)W_diag,   wdiag4, n4_wdiag);

    // G1+G2 fused
    mma_gemm_dual<<<dim3(NB1 + DD / 128, BB / 128), 256, MMA_SMEM>>>(
        (const float*)feat4,
        (const float*)wcov4,  b_cov,  lrc,
        (const float*)wdiag4, b_diag, stdv,
        BB, DD);

    // W_cls rounding only feeds G3 -> overlap with dual's tail
    const int n4_wcls = CC * DD / 4;
    round_tf32_one<<<(n4_wcls + 255) / 256, 256>>>((const float4*)W_cls, wcls4, n4_wcls);

    // pre_logits (one block per b, lrc read once)
    prelogits_kernel<<<BB, 256>>>(features, lrc, stdv, noise_diag, noise_lr, pre);

    // G3: out = (pre @ W_cls^T + b_cls) / 1.5
    mma_gemm_g3<<<dim3((CC + 127) / 128, (BB * SS) / 128), 256, MMA_SMEM>>>(
        pre, (const float*)wcls4, b_cls, out, BB * SS, CC, DD);
}

// round 16
// speedup vs baseline: 1.0074x; 1.0074x over previous
#include <cuda_runtime.h>
#include <math.h>
#include <stdint.h>

// Problem constants
#define BB 1024
#define SS 64
#define DD 512
#define RR 16
#define CC 1000

// ---------------------------------------------------------------------------
// Scratch (__device__ globals; float4 for 16B alignment needed by cp.async)
// ---------------------------------------------------------------------------
__device__ float4 g_lrc4  [(size_t)BB * DD * RR / 4];  // low_rank_cov [B, D*R]
__device__ float4 g_std4  [(size_t)BB * DD / 4];       // diagonal_std [B, D]
__device__ float4 g_pre4  [(size_t)BB * SS * DD / 4];  // pre_logits [B*S, D] (tf32-rounded)
__device__ float4 g_wcov4 [(size_t)DD * RR * DD / 4];  // tf32-rounded W_cov
__device__ float4 g_wcls4 [(size_t)CC * DD / 4];       // tf32-rounded W_cls
__device__ float4 g_wdiag4[(size_t)DD * DD / 4];       // tf32-rounded W_diag
__device__ float4 g_feat4 [(size_t)BB * DD / 4];       // tf32-rounded features

// ---------------------------------------------------------------------------
// Helpers
// ---------------------------------------------------------------------------
__device__ __forceinline__ uint32_t smem_u32(const void* p) {
    uint32_t a;
    asm("{ .reg .u64 t; cvta.to.shared.u64 t, %1; cvt.u32.u64 %0, t; }"
        : "=r"(a) : "l"(p));
    return a;
}
__device__ __forceinline__ float rtf32(float x) {  // round-to-nearest tf32
    uint32_t o; asm("cvt.rna.tf32.f32 %0, %1;" : "=r"(o) : "f"(x));
    return __uint_as_float(o);
}
__device__ __forceinline__ void cpa16(uint32_t dst, const void* src, uint32_t sz) {
    asm volatile("cp.async.cg.shared.global [%0], [%1], 16, %2;"
                 :: "r"(dst), "l"(src), "r"(sz) : "memory");
}
// m16n8k8 tf32 MMA (legacy HMMA path; legal on base sm_103 target)
__device__ __forceinline__ void mma8(float* d, const uint32_t* a, const uint32_t* b) {
    asm volatile(
        "mma.sync.aligned.m16n8k8.row.col.f32.tf32.tf32.f32 "
        "{%0,%1,%2,%3}, {%4,%5,%6,%7}, {%8,%9}, {%0,%1,%2,%3};"
        : "+f"(d[0]), "+f"(d[1]), "+f"(d[2]), "+f"(d[3])
        : "r"(a[0]), "r"(a[1]), "r"(a[2]), "r"(a[3]), "r"(b[0]), "r"(b[1]));
}
// ldmatrix x4 (b16 view; one m8n8.b16 tile == one 8x4 tf32 fragment tile)
__device__ __forceinline__ void ldsm4(uint32_t* r, uint32_t addr) {
    asm volatile("ldmatrix.sync.aligned.m8n8.x4.shared.b16 {%0,%1,%2,%3}, [%4];"
        : "=r"(r[0]), "=r"(r[1]), "=r"(r[2]), "=r"(r[3]) : "r"(addr));
}

#define KSLAB 32
#define STGS  3
#define AHEAD 2
#define PAD   36
#define STAGE_FLOATS (2 * 128 * PAD)
#define BOFF  (128 * PAD)
#define MMA_SMEM (STGS * STAGE_FLOATS * 4 + 512)   // 111104 B -> 2 CTAs/SM

// ---------------------------------------------------------------------------
// G3 kernel: C = A @ B^T + bias, EPI = x*(2/3).  N=1000 needs guards.
// 8 warps (4m x 2n), warp 32x64, 256 threads, 2 CTAs/SM (16 warps/SM).
// ---------------------------------------------------------------------------
__global__ __launch_bounds__(256, 2) void mma_gemm_g3(
    const float* __restrict__ A, const float* __restrict__ Bm,
    const float* __restrict__ bias, float* __restrict__ Cm,
    int M, int N, int K)
{
    extern __shared__ float sm[];
    float* s_bias = sm + STGS * STAGE_FLOATS;

    const int tid = threadIdx.x;
    const int bm  = blockIdx.y * 128;
    const int bn  = blockIdx.x * 128;

    if (tid < 128) s_bias[tid] = (bn + tid < N) ? bias[bn + tid] : 0.f;

    const int wid = tid >> 5, lane = tid & 31;
    const int wm  = (wid & 3) * 32;
    const int wn  = (wid >> 2) * 64;
    const int g   = lane >> 2;
    const int t   = lane & 3;

    const uint32_t smb = smem_u32(sm);

    const int tile = lane >> 3, rit = lane & 7;
    uint32_t aoff[2], boff[4];
#pragma unroll
    for (int mt = 0; mt < 2; mt++)
        aoff[mt] = (uint32_t)(((wm + mt * 16 + ((tile & 1) << 3) + rit) * PAD
                               + ((tile >> 1) << 2)) * 4);
#pragma unroll
    for (int p = 0; p < 4; p++)
        boff[p] = (uint32_t)((BOFF + (wn + p * 16 + ((tile >> 1) << 3) + rit) * PAD
                               + ((tile & 1) << 2)) * 4);

    auto load_slab = [&](int s, int slab) {
        const int k0 = slab * KSLAB;
        const uint32_t abase = smb + (uint32_t)(s * STAGE_FLOATS) * 4u;
        const uint32_t bbase = abase + BOFF * 4u;
#pragma unroll
        for (int q = 0; q < 4; q++) {
            int idx = tid + q * 256;
            int m = idx >> 3, kc = idx & 7;
            cpa16(abase + (uint32_t)(m * PAD + kc * 4) * 4u,
                  A + (size_t)(bm + m) * K + k0 + kc * 4, 16);
        }
#pragma unroll
        for (int q = 0; q < 4; q++) {
            int idx = tid + q * 256;
            int n = idx >> 3, kc = idx & 7;
            int gn = bn + n;
            uint32_t sz = (gn < N) ? 16u : 0u;
            int gc = (gn < N) ? gn : (N - 1);
            cpa16(bbase + (uint32_t)(n * PAD + kc * 4) * 4u,
                  Bm + (size_t)gc * K + k0 + kc * 4, sz);
        }
    };

    float acc[2][8][4];
#pragma unroll
    for (int i = 0; i < 2; i++)
#pragma unroll
        for (int j = 0; j < 8; j++)
#pragma unroll
            for (int c = 0; c < 4; c++) acc[i][j][c] = 0.f;

    const int nslab = K / KSLAB;
    for (int p = 0; p < AHEAD; p++) {
        load_slab(p, p);
        asm volatile("cp.async.commit_group;" ::: "memory");
    }

    for (int j = 0; j < nslab; j++) {
        asm volatile("cp.async.wait_group 1;" ::: "memory");
        __syncthreads();
        if (j + AHEAD < nslab) load_slab((j + AHEAD) % STGS, j + AHEAD);
        asm volatile("cp.async.commit_group;" ::: "memory");

        const uint32_t stg = smb + (uint32_t)((j % STGS) * STAGE_FLOATS) * 4u;

#pragma unroll
        for (int ks = 0; ks < 4; ks++) {
            const uint32_t kb = stg + (uint32_t)ks * 32u;
            uint32_t af[2][4], bf[4][4];
            ldsm4(af[0], kb + aoff[0]);
            ldsm4(af[1], kb + aoff[1]);
#pragma unroll
            for (int p = 0; p < 4; p++) ldsm4(bf[p], kb + boff[p]);
#pragma unroll
            for (int mt = 0; mt < 2; mt++)
#pragma unroll
                for (int nt = 0; nt < 8; nt++)
                    mma8(acc[mt][nt], af[mt], &bf[nt >> 1][(nt & 1) << 1]);
        }
    }

#pragma unroll
    for (int mt = 0; mt < 2; mt++) {
        const int r0 = bm + wm + mt * 16 + g;
#pragma unroll
        for (int nt = 0; nt < 8; nt++) {
            const int lc = wn + nt * 8 + 2 * t;
            const int gc = bn + lc;
            float b0 = s_bias[lc], b1 = s_bias[lc + 1];
            float v00 = (acc[mt][nt][0] + b0) * (2.0f / 3.0f);
            float v01 = (acc[mt][nt][1] + b1) * (2.0f / 3.0f);
            float v10 = (acc[mt][nt][2] + b0) * (2.0f / 3.0f);
            float v11 = (acc[mt][nt][3] + b1) * (2.0f / 3.0f);
            if (gc + 1 < N) {
                *(float2*)(Cm + (size_t)r0 * N + gc)       = make_float2(v00, v01);
                *(float2*)(Cm + (size_t)(r0 + 8) * N + gc) = make_float2(v10, v11);
            } else if (gc < N) {
                Cm[(size_t)r0 * N + gc]       = v00;
                Cm[(size_t)(r0 + 8) * N + gc] = v10;
            }
        }
    }
}

// ---------------------------------------------------------------------------
// Dual GEMM (G1 + G2 in one launch): blocks x<NB1 -> lrc (plain epi),
// blocks x>=NB1 -> stdv (softplus epi). All N multiples of 128 (no guards).
// ---------------------------------------------------------------------------
#define NB1 64    // (DD*RR)/128 n-blocks for G1; G2 adds DD/128 = 4

__global__ __launch_bounds__(256, 2) void mma_gemm_dual(
    const float* __restrict__ A,
    const float* __restrict__ B1, const float* __restrict__ bias1,
    float* __restrict__ C1,
    const float* __restrict__ B2, const float* __restrict__ bias2,
    float* __restrict__ C2,
    int M, int K)
{
    extern __shared__ float sm[];
    float* s_bias = sm + STGS * STAGE_FLOATS;

    const int tid = threadIdx.x;
    const int bm  = blockIdx.y * 128;
    const bool g2 = (blockIdx.x >= NB1);
    const int bn  = (g2 ? (blockIdx.x - NB1) : blockIdx.x) * 128;
    const float* Bm   = g2 ? B2 : B1;
    const float* bias = g2 ? bias2 : bias1;
    float* Cm         = g2 ? C2 : C1;
    const int N       = g2 ? DD : DD * RR;

    if (tid < 128) s_bias[tid] = bias[bn + tid];

    const int wid = tid >> 5, lane = tid & 31;
    const int wm  = (wid & 3) * 32;
    const int wn  = (wid >> 2) * 64;
    const int g   = lane >> 2;
    const int t   = lane & 3;

    const uint32_t smb = smem_u32(sm);

    const int tile = lane >> 3, rit = lane & 7;
    uint32_t aoff[2], boff[4];
#pragma unroll
    for (int mt = 0; mt < 2; mt++)
        aoff[mt] = (uint32_t)(((wm + mt * 16 + ((tile & 1) << 3) + rit) * PAD
                               + ((tile >> 1) << 2)) * 4);
#pragma unroll
    for (int p = 0; p < 4; p++)
        boff[p] = (uint32_t)((BOFF + (wn + p * 16 + ((tile >> 1) << 3) + rit) * PAD
                               + ((tile & 1) << 2)) * 4);

    auto load_slab = [&](int s, int slab) {
        const int k0 = slab * KSLAB;
        const uint32_t abase = smb + (uint32_t)(s * STAGE_FLOATS) * 4u;
        const uint32_t bbase = abase + BOFF * 4u;
#pragma unroll
        for (int q = 0; q < 4; q++) {
            int idx = tid + q * 256;
            int m = idx >> 3, kc = idx & 7;
            cpa16(abase + (uint32_t)(m * PAD + kc * 4) * 4u,
                  A + (size_t)(bm + m) * K + k0 + kc * 4, 16);
        }
#pragma unroll
        for (int q = 0; q < 4; q++) {
            int idx = tid + q * 256;
            int n = idx >> 3, kc = idx & 7;
            cpa16(bbase + (uint32_t)(n * PAD + kc * 4) * 4u,
                  Bm + (size_t)(bn + n) * K + k0 + kc * 4, 16);
        }
    };

    float acc[2][8][4];
#pragma unroll
    for (int i = 0; i < 2; i++)
#pragma unroll
        for (int j = 0; j < 8; j++)
#pragma unroll
            for (int c = 0; c < 4; c++) acc[i][j][c] = 0.f;

    const int nslab = K / KSLAB;
    for (int p = 0; p < AHEAD; p++) {
        load_slab(p, p);
        asm volatile("cp.async.commit_group;" ::: "memory");
    }

    for (int j = 0; j < nslab; j++) {
        asm volatile("cp.async.wait_group 1;" ::: "memory");
        __syncthreads();
        if (j + AHEAD < nslab) load_slab((j + AHEAD) % STGS, j + AHEAD);
        asm volatile("cp.async.commit_group;" ::: "memory");

        const uint32_t stg = smb + (uint32_t)((j % STGS) * STAGE_FLOATS) * 4u;

#pragma unroll
        for (int ks = 0; ks < 4; ks++) {
            const uint32_t kb = stg + (uint32_t)ks * 32u;
            uint32_t af[2][4], bf[4][4];
            ldsm4(af[0], kb + aoff[0]);
            ldsm4(af[1], kb + aoff[1]);
#pragma unroll
            for (int p = 0; p < 4; p++) ldsm4(bf[p], kb + boff[p]);
#pragma unroll
            for (int mt = 0; mt < 2; mt++)
#pragma unroll
                for (int nt = 0; nt < 8; nt++)
                    mma8(acc[mt][nt], af[mt], &bf[nt >> 1][(nt & 1) << 1]);
        }
    }

#pragma unroll
    for (int mt = 0; mt < 2; mt++) {
        const int r0 = bm + wm + mt * 16 + g;
#pragma unroll
        for (int nt = 0; nt < 8; nt++) {
            const int lc = wn + nt * 8 + 2 * t;
            const int gc = bn + lc;
            float b0 = s_bias[lc], b1 = s_bias[lc + 1];
            float v00 = acc[mt][nt][0] + b0, v01 = acc[mt][nt][1] + b1;
            float v10 = acc[mt][nt][2] + b0, v11 = acc[mt][nt][3] + b1;
            if (g2) {   // uniform branch per block
                v00 = fmaxf(v00, 0.f) + log1pf(expf(-fabsf(v00))) + 1e-3f;
                v01 = fmaxf(v01, 0.f) + log1pf(expf(-fabsf(v01))) + 1e-3f;
                v10 = fmaxf(v10, 0.f) + log1pf(expf(-fabsf(v10))) + 1e-3f;
                v11 = fmaxf(v11, 0.f) + log1pf(expf(-fabsf(v11))) + 1e-3f;
            }
            *(float2*)(Cm + (size_t)r0 * N + gc)       = make_float2(v00, v01);
            *(float2*)(Cm + (size_t)(r0 + 8) * N + gc) = make_float2(v10, v11);
        }
    }
}

// ---------------------------------------------------------------------------
// tf32 RN rounding: 3-segment (pre-dual inputs) + single-segment (wcls)
// ---------------------------------------------------------------------------
__global__ void round_tf32_seg3(
    const float4* __restrict__ s0, float4* __restrict__ d0, int n0,
    const float4* __restrict__ s1, float4* __restrict__ d1, int n1,
    const float4* __restrict__ s2, float4* __restrict__ d2, int n2)
{
    int i = blockIdx.x * blockDim.x + threadIdx.x;
    const float4* s; float4* d; int k;
    if (i < n0)                { s = s0; d = d0; k = i; }
    else if (i < n0 + n1)      { s = s1; d = d1; k = i - n0; }
    else if (i < n0 + n1 + n2) { s = s2; d = d2; k = i - n0 - n1; }
    else return;
    float4 v = s[k];
    v.x = rtf32(v.x); v.y = rtf32(v.y); v.z = rtf32(v.z); v.w = rtf32(v.w);
    d[k] = v;
}

__global__ void round_tf32_one(const float4* __restrict__ s, float4* __restrict__ d, int n)
{
    int i = blockIdx.x * blockDim.x + threadIdx.x;
    if (i >= n) return;
    float4 v = s[i];
    v.x = rtf32(v.x); v.y = rtf32(v.y); v.z = rtf32(v.z); v.w = rtf32(v.w);
    d[i] = v;
}

// ---------------------------------------------------------------------------
// pre[b,s,d] = f + std*nd + sum_r lrc*nlr   (tf32-rounded output)
// R10 config: thread owns 2 d (lr[2][16] = 32 regs), grid BB x 2 s-halves,
// 3 CTAs/SM, 32 s-iters/thread, unroll 4, zero LDS.
// ---------------------------------------------------------------------------
__global__ __launch_bounds__(256, 3) void prelogits_kernel(
    const float* __restrict__ features, const float* __restrict__ lrc,
    const float* __restrict__ stdv, const float* __restrict__ nd,
    const float* __restrict__ nlr, float* __restrict__ pre)
{
    const int b   = blockIdx.x >> 1;
    const int sh  = blockIdx.x & 1;
    const int tid = threadIdx.x;
    const int d0  = tid << 1;

    float lr[2][16];
    const float4* lp = (const float4*)(lrc + ((size_t)b * DD + d0) * RR);
#pragma unroll
    for (int i = 0; i < 2; i++)
#pragma unroll
        for (int q = 0; q < 4; q++) {
            float4 v = lp[i * 4 + q];
            lr[i][q * 4 + 0] = v.x; lr[i][q * 4 + 1] = v.y;
            lr[i][q * 4 + 2] = v.z; lr[i][q * 4 + 3] = v.w;
        }
    const float2 f2  = *(const float2*)(features + (size_t)b * DD + d0);
    const float2 sd2 = *(const float2*)(stdv     + (size_t)b * DD + d0);

    const size_t row0 = (size_t)b * SS + sh * 32;
#pragma unroll 4
    for (int si = 0; si < 32; si++) {
        const size_t row = row0 + si;
        float nr[16];
        const float4* np = (const float4*)(nlr + row * RR);
#pragma unroll
        for (int q = 0; q < 4; q++) {
            float4 v = np[q];   // uniform across block -> warp broadcast
            nr[q * 4 + 0] = v.x; nr[q * 4 + 1] = v.y;
            nr[q * 4 + 2] = v.z; nr[q * 4 + 3] = v.w;
        }
        const float2 ndv = *(const float2*)(nd + row * DD + d0);
        float a0 = fmaf(sd2.x, ndv.x, f2.x);
        float a1 = fmaf(sd2.y, ndv.y, f2.y);
#pragma unroll
        for (int r = 0; r < 16; r++) {
            a0 = fmaf(lr[0][r], nr[r], a0);
            a1 = fmaf(lr[1][r], nr[r], a1);
        }
        *(float2*)(pre + row * DD + d0) = make_float2(rtf32(a0), rtf32(a1));
    }
}

// ---------------------------------------------------------------------------
extern "C" void kernel_launch(void* const* d_in, const int* in_sizes, int n_in,
                              void* d_out, int out_size)
{
    const float* features   = (const float*)d_in[0];
    const float* W_cov      = (const float*)d_in[1];
    const float* b_cov      = (const float*)d_in[2];
    const float* W_diag     = (const float*)d_in[3];
    const float* b_diag     = (const float*)d_in[4];
    const float* W_cls      = (const float*)d_in[5];
    const float* b_cls      = (const float*)d_in[6];
    const float* noise_diag = (const float*)d_in[7];
    const float* noise_lr   = (const float*)d_in[8];
    float* out = (float*)d_out;

    float4 *lrc4, *std4, *pre4, *wcov4, *wcls4, *wdiag4, *feat4;
    cudaGetSymbolAddress((void**)&lrc4,   g_lrc4);
    cudaGetSymbolAddress((void**)&std4,   g_std4);
    cudaGetSymbolAddress((void**)&pre4,   g_pre4);
    cudaGetSymbolAddress((void**)&wcov4,  g_wcov4);
    cudaGetSymbolAddress((void**)&wcls4,  g_wcls4);
    cudaGetSymbolAddress((void**)&wdiag4, g_wdiag4);
    cudaGetSymbolAddress((void**)&feat4,  g_feat4);
    float* lrc  = (float*)lrc4;
    float* stdv = (float*)std4;
    float* pre  = (float*)pre4;

    cudaFuncSetAttribute(mma_gemm_g3,   cudaFuncAttributeMaxDynamicSharedMemorySize, MMA_SMEM);
    cudaFuncSetAttribute(mma_gemm_dual, cudaFuncAttributeMaxDynamicSharedMemorySize, MMA_SMEM);

    // Round the dual-GEMM inputs first (critical path)
    const int n4_feat  = BB * DD / 4;
    const int n4_wcov  = DD * RR * DD / 4;
    const int n4_wdiag = DD * DD / 4;
    const int n4_pre3  = n4_feat + n4_wcov + n4_wdiag;
    round_tf32_seg3<<<(n4_pre3 + 255) / 256, 256>>>(
        (const float4*)features, feat4,  n4_feat,
        (const float4*)W_cov,    wcov4,  n4_wcov,
        (const float4*)W_diag,   wdiag4, n4_wdiag);

    // G1+G2 fused
    mma_gemm_dual<<<dim3(NB1 + DD / 128, BB / 128), 256, MMA_SMEM>>>(
        (const float*)feat4,
        (const float*)wcov4,  b_cov,  lrc,
        (const float*)wdiag4, b_diag, stdv,
        BB, DD);

    // W_cls rounding only feeds G3 -> overlap with dual's tail
    const int n4_wcls = CC * DD / 4;
    round_tf32_one<<<(n4_wcls + 255) / 256, 256>>>((const float4*)W_cls, wcls4, n4_wcls);

    // pre_logits (R10 config: 2 s-half blocks per b)
    prelogits_kernel<<<BB * 2, 256>>>(features, lrc, stdv, noise_diag, noise_lr, pre);

    // G3: out = (pre @ W_cls^T + b_cls) / 1.5
    mma_gemm_g3<<<dim3((CC + 127) / 128, (BB * SS) / 128), 256, MMA_SMEM>>>(
        pre, (const float*)wcls4, b_cls, out, BB * SS, CC, DD);
}